// round 12
// baseline (speedup 1.0000x reference)
#include <cuda_runtime.h>
#include <math.h>

#define NX 64
#define NUN 256
#define NY 32
#define NZ 384        // 2*NX + NUN
#define BATCH 32768
#define NSTATE 384    // 128 (z = x||u) + 256 (w)
#define EPB 64        // batch elements per block (32 pairs)
#define TB 128        // 4 warps; warp owns 8 pairs
#define SSTRIDE 33    // state row stride in ULL (conflict-free for tg16 split)

typedef unsigned long long ULL;

// ---------------- f32x2 / misc helpers ----------------------------------
__device__ __forceinline__ ULL ffma2(ULL a, ULL b, ULL c) {
    ULL d; asm("fma.rn.f32x2 %0, %1, %2, %3;" : "=l"(d) : "l"(a), "l"(b), "l"(c)); return d;
}
__device__ __forceinline__ ULL fadd2(ULL a, ULL b) {
    ULL d; asm("add.rn.f32x2 %0, %1, %2;" : "=l"(d) : "l"(a), "l"(b)); return d;
}
__device__ __forceinline__ ULL pack2(float lo, float hi) {
    ULL d; asm("mov.b64 %0, {%1,%2};" : "=l"(d) : "f"(lo), "f"(hi)); return d;
}
__device__ __forceinline__ void unpack2(ULL v, float& lo, float& hi) {
    asm("mov.b64 {%0,%1}, %2;" : "=f"(lo), "=f"(hi) : "l"(v));
}
__device__ __forceinline__ ULL shfl_xor64(ULL v, int m) {
    return __shfl_xor_sync(0xFFFFFFFFu, v, m, 32);
}
__device__ __forceinline__ float tanh_fast(float x) {
    float y; asm("tanh.approx.f32 %0, %1;" : "=f"(y) : "f"(x)); return y;
}

// ---------------- device scratch (no cudaMalloc allowed) ----------------
__device__ __align__(16) float g_lT1[NZ * 64];
__device__ __align__(16) float g_lT2[NZ * 32];
__device__ __align__(16) float g_M1[NZ * 64];
__device__ __align__(16) float g_M2[NZ * 32];
__device__ __align__(16) float g_H[256 * 320];      // H[64+r][c], c in [0,320)
// per-chunk block (3152 floats):
//   [0,3072)      coefT[t][k]: coefficient for unit k at input row t
//   [3072,3080)   bias (b_w/lam) for k=0..7
//   [3080,3108)   compact diag: dg(k,j) at 3080 + k(k-1)/2 + j, j<k
//   [3108,3152)   pad
__device__ __align__(16) float g_CHUNK[32 * 3152];
// y-weights: rows 0..63 = C2T (x part), 64..319 = D21T (w part)
__device__ __align__(16) float g_YWP[320 * 32];

// ---------------- setup kernels (batch-independent weights) --------------

__global__ void k_build_lT(const float* __restrict__ B2, const float* __restrict__ C2,
                           const float* __restrict__ D12, const float* __restrict__ D21,
                           const float* __restrict__ St) {
    int r = blockIdx.x;      // 0..383
    int k = threadIdx.x;     // 0..63
    float v1;
    if (r < 64) {
        float s = 0.f;
        for (int m = 0; m < 32; m++) s += St[k * 32 + m] * C2[m * 64 + r];
        v1 = s;
    } else if (r < 320) {
        int rr = r - 64;
        float s = 0.f;
        for (int m = 0; m < 32; m++) s += St[k * 32 + m] * D21[m * 256 + rr];
        v1 = s - D12[rr * 64 + k];
    } else {
        v1 = B2[(r - 320) * 64 + k];
    }
    g_lT1[r * 64 + k] = v1;
    if (k < 32) {
        float v2;
        if (r < 64)        v2 = C2[k * 64 + r];
        else if (r < 320)  v2 = D21[k * 256 + (r - 64)];
        else               v2 = 0.f;
        g_lT2[r * 32 + k] = v2;
    }
}

__global__ void k_build_M(const float* __restrict__ Rinv, const float* __restrict__ Q) {
    int r = blockIdx.x, k = threadIdx.x;
    float s = 0.f;
    for (int t = 0; t < 64; t++) s += g_lT1[r * 64 + t] * Rinv[t * 64 + k];
    g_M1[r * 64 + k] = s;
    if (k < 32) {
        float s2 = 0.f;
        for (int t = 0; t < 32; t++) s2 += g_lT2[r * 32 + t] * Q[t * 32 + k];
        g_M2[r * 32 + k] = s2;
    }
}

__global__ void k_build_H(const float* __restrict__ X) {
    int idx = blockIdx.x * blockDim.x + threadIdx.x;
    if (idx >= 256 * 320) return;
    int r = idx / 320, c = idx % 320;
    int a = 64 + r;
    float h = 0.f;
    for (int t = 0; t < NZ; t++) h += X[t * NZ + a] * X[t * NZ + c];
    if (c == a) h += 0.001f;
    float h1 = 0.f;
    for (int k = 0; k < 64; k++) h1 += g_M1[a * 64 + k] * g_lT1[c * 64 + k];
    float h2 = 0.f;
    for (int k = 0; k < 32; k++) h2 += g_M2[a * 32 + k] * g_lT2[c * 32 + k];
    g_H[idx] = h + h1 - h2;
}

// grid 320: i<64 -> C2T rows of g_YWP; else unit uu -> g_CHUNK slices + D21T
__global__ void k_finalize(const float* __restrict__ D12, const float* __restrict__ D21,
                           const float* __restrict__ C2, const float* __restrict__ b) {
    int i = blockIdx.x;
    int tx = threadIdx.x;
    if (i < 64) {
        if (tx < 32) g_YWP[i * 32 + tx] = C2[tx * 64 + i];
        return;
    }
    int uu = i - 64;  // 0..255
    __shared__ float s_inv;
    if (tx == 0) {
        float lam = 0.5f * g_H[uu * 320 + 64 + uu];
        s_inv = 1.f / lam;
    }
    __syncthreads();
    float inv = s_inv;
    int c = uu >> 3, k = uu & 7;
    float* chunk = g_CHUNK + (size_t)c * 3152;
    for (int t = tx; t < NSTATE; t += blockDim.x) {
        float val;
        if (t < 64) {
            val = -g_H[uu * 320 + t] * inv;                 // C_1 / lam
        } else if (t < 128) {
            val = D12[uu * 64 + (t - 64)] * inv;            // D_12 / lam
        } else {
            int j = t - 128;
            val = (uu >= 1 && j <= uu - 2) ? (-g_H[(uu - 1) * 320 + 64 + j]) * inv : 0.f;
        }
        chunk[t * 8 + k] = val;                             // [t][unit] layout
    }
    // compact within-chunk diag: entries (k, j) with j < k
    if (tx < k) {
        int j = c * 8 + tx;   // global column
        float val = (uu >= 1 && j <= uu - 2) ? (-g_H[(uu - 1) * 320 + 64 + j]) * inv : 0.f;
        chunk[3080 + (k * (k - 1)) / 2 + tx] = val;
    }
    if (tx == 0) chunk[3072 + k] = b[64 + uu] * inv;
    if (tx < 32) g_YWP[(64 + uu) * 32 + tx] = D21[tx * 256 + uu];
}

// ---------------- main kernel ---------------------------------------------
// 64 elems = 32 f32x2 pairs per block, 128 threads = 4 warps, warp owns 8
// pairs. lane = pg*16 + tg: pg in {0,1} -> 4 pairs, tg in 0..15 splits the
// t-dimension 16 ways. Lane register tile: 8 units x 4 pairs (32 f32x2 accs).
// Per t-iter: 4 LDS.64 state (native pairs) + 2 LDS.128 coef (8 floats)
// -> 32 FFMA2. Reduce over tg with 4 shfl_xor rounds; diag+tanh on tg==0
// lanes; w-stores warp-local. 2 block barriers/chunk (coef staging only).
//
// Shared layout (ULL units):
#define SM_STATE 0                          // ULL[384][33]   = 12672
#define SM_CA    12672                      // float[376*4]   = 752 ULL
#define SM_CB    (SM_CA + 752)              // float[376*4]   = 752 ULL
#define SM_TOTAL (SM_CB + 752)              // 14176 ULL = 113408 B -> 2 blocks/SM

__global__ void __launch_bounds__(TB, 2)
k_main(const float* __restrict__ u, const float* __restrict__ x0,
       const float* __restrict__ b, float* __restrict__ out) {
    extern __shared__ ULL sh[];
    ULL*   s_state = sh;
    float* s_cA    = (float*)(sh + SM_CA);
    float* s_cB    = (float*)(sh + SM_CB);

    const int tid  = threadIdx.x;
    const int lane = tid & 31;
    const int warp = tid >> 5;
    const int tg   = lane & 15;
    const int pg   = lane >> 4;
    const int pairbase = warp * 8 + pg * 4;   // first of this lane's 4 pairs
    const int b0   = blockIdx.x * EPB;

    // ---- load z = [x(64) | u(64)] coalesced, transposed to pair layout ----
    {
        float* st = (float*)s_state;
#pragma unroll 4
        for (int i = 0; i < 32; i++) {
            int idx = i * TB + tid;          // 0..4095
            int e = idx >> 6, k = idx & 63;
            st[k * 66 + e]        = x0[(size_t)b0 * 64 + idx];
            st[(64 + k) * 66 + e] = u[(size_t)b0 * 64 + idx];
        }
    }

    // ================= main chunk loop =================
    for (int c = 0; c < 32; c++) {
        const float* gchunk = g_CHUNK + (size_t)c * 3152;
        const int T = 128 + 8 * c;

        __syncthreads();   // bar1: prior p-loop done reading coef buffers (and z visible)

        // ---- stage coef chunk c: [t][0..3] -> s_cA, [t][4..7] -> s_cB ----
        for (int idx = tid; idx < T * 2; idx += TB) {
            int t = idx >> 1, h = idx & 1;
            float4 v = __ldg((const float4*)gchunk + t * 2 + h);
            ((float4*)(h ? s_cB : s_cA))[t] = v;
        }

        // ---- prefetch bias(8) + compact diag(28) into regs ----
        float dgb[36];
        {
            const float4* ds = (const float4*)(gchunk + 3072);
#pragma unroll
            for (int i = 0; i < 9; i++) {
                float4 v = __ldg(ds + i);
                dgb[4 * i + 0] = v.x; dgb[4 * i + 1] = v.y;
                dgb[4 * i + 2] = v.z; dgb[4 * i + 3] = v.w;
            }
        }
        __syncthreads();   // bar2: staged coef visible

        // ---- t-loop: lane handles t = tg, tg+16, ... ----
        ULL acc[32];       // acc[k*4+j]: unit k, pair j
#pragma unroll
        for (int i = 0; i < 32; i++) acc[i] = 0ull;

        const ULL* sp   = s_state + (size_t)tg * SSTRIDE + pairbase;
        const float4* ca = (const float4*)s_cA + tg;
        const float4* cb = (const float4*)s_cB + tg;
        for (int t = tg; t < T; t += 16) {
            ULL sv0 = sp[0], sv1 = sp[1], sv2 = sp[2], sv3 = sp[3];
            float4 a4 = *ca;
            float4 b4 = *cb;
            sp += SSTRIDE * 16; ca += 16; cb += 16;
            ULL c0 = pack2(a4.x, a4.x), c1 = pack2(a4.y, a4.y);
            ULL c2 = pack2(a4.z, a4.z), c3 = pack2(a4.w, a4.w);
            ULL c4 = pack2(b4.x, b4.x), c5 = pack2(b4.y, b4.y);
            ULL c6 = pack2(b4.z, b4.z), c7 = pack2(b4.w, b4.w);
#define ACC_K(K, CK) \
            acc[(K)*4+0] = ffma2(sv0, CK, acc[(K)*4+0]); \
            acc[(K)*4+1] = ffma2(sv1, CK, acc[(K)*4+1]); \
            acc[(K)*4+2] = ffma2(sv2, CK, acc[(K)*4+2]); \
            acc[(K)*4+3] = ffma2(sv3, CK, acc[(K)*4+3]);
            ACC_K(0, c0) ACC_K(1, c1) ACC_K(2, c2) ACC_K(3, c3)
            ACC_K(4, c4) ACC_K(5, c5) ACC_K(6, c6) ACC_K(7, c7)
#undef ACC_K
        }

        // ---- reduce over tg: 4 shfl_xor rounds ----
#pragma unroll
        for (int i = 0; i < 32; i++) {
            acc[i] = fadd2(acc[i], shfl_xor64(acc[i], 1));
            acc[i] = fadd2(acc[i], shfl_xor64(acc[i], 2));
            acc[i] = fadd2(acc[i], shfl_xor64(acc[i], 4));
            acc[i] = fadd2(acc[i], shfl_xor64(acc[i], 8));
        }

        // ---- serial 8x8 diag + tanh + store w (tg==0 lanes only) ----
        if (tg == 0) {
            ULL wl[32];
#pragma unroll
            for (int k = 0; k < 8; k++) {
                ULL bk = pack2(dgb[k], dgb[k]);
                ULL s0 = fadd2(acc[k * 4 + 0], bk);
                ULL s1 = fadd2(acc[k * 4 + 1], bk);
                ULL s2 = fadd2(acc[k * 4 + 2], bk);
                ULL s3 = fadd2(acc[k * 4 + 3], bk);
#pragma unroll
                for (int ju = 0; ju < 7; ju++) {
                    if (ju < k) {
                        float d = dgb[8 + (k * (k - 1)) / 2 + ju];
                        ULL dd = pack2(d, d);
                        s0 = ffma2(wl[ju * 4 + 0], dd, s0);
                        s1 = ffma2(wl[ju * 4 + 1], dd, s1);
                        s2 = ffma2(wl[ju * 4 + 2], dd, s2);
                        s3 = ffma2(wl[ju * 4 + 3], dd, s3);
                    }
                }
                float l0, h0, l1, h1, l2, h2, l3, h3;
                unpack2(s0, l0, h0); unpack2(s1, l1, h1);
                unpack2(s2, l2, h2); unpack2(s3, l3, h3);
                wl[k * 4 + 0] = pack2(tanh_fast(l0), tanh_fast(h0));
                wl[k * 4 + 1] = pack2(tanh_fast(l1), tanh_fast(h1));
                wl[k * 4 + 2] = pack2(tanh_fast(l2), tanh_fast(h2));
                wl[k * 4 + 3] = pack2(tanh_fast(l3), tanh_fast(h3));
                ULL* wrow = s_state + (size_t)(128 + c * 8 + k) * SSTRIDE + pairbase;
                wrow[0] = wl[k * 4 + 0]; wrow[1] = wl[k * 4 + 1];
                wrow[2] = wl[k * 4 + 2]; wrow[3] = wl[k * 4 + 3];
            }
        }
        __syncwarp();   // w(c) visible within warp (state cols are warp-private)
    }

    // ================= y-tail: y = x@C2T + w@D21T =================
    // lane covers m = {tg*2, tg*2+1} for its 4 pairs; rows staged in 4 rounds.
    ULL yacc[8];   // yacc[mm*4 + j]
#pragma unroll
    for (int i = 0; i < 8; i++) yacc[i] = 0ull;
    float* yc = (float*)(sh + SM_CA);   // 3008-float region (needs 2560)

    for (int r = 0; r < 4; r++) {
        __syncthreads();
        {
            const float4* src = (const float4*)g_YWP + r * 640;
#pragma unroll
            for (int i = 0; i < 5; i++) ((float4*)yc)[i * TB + tid] = __ldg(src + i * TB + tid);
        }
        __syncthreads();
#pragma unroll 2
        for (int i = 0; i < 80; i++) {
            int g = r * 80 + i;
            int srow = (g < 64) ? g : g + 64;
            const ULL* sp2 = s_state + (size_t)srow * SSTRIDE + pairbase;
            ULL sv0 = sp2[0], sv1 = sp2[1], sv2 = sp2[2], sv3 = sp2[3];
            float2 cm = *(const float2*)(yc + i * 32 + tg * 2);
            ULL cm0 = pack2(cm.x, cm.x), cm1 = pack2(cm.y, cm.y);
            yacc[0] = ffma2(sv0, cm0, yacc[0]);
            yacc[1] = ffma2(sv1, cm0, yacc[1]);
            yacc[2] = ffma2(sv2, cm0, yacc[2]);
            yacc[3] = ffma2(sv3, cm0, yacc[3]);
            yacc[4] = ffma2(sv0, cm1, yacc[4]);
            yacc[5] = ffma2(sv1, cm1, yacc[5]);
            yacc[6] = ffma2(sv2, cm1, yacc[6]);
            yacc[7] = ffma2(sv3, cm1, yacc[7]);
        }
    }

    // ---- output: lane stores m-pair (tg*2, tg*2+1) for its 8 elems ----
    {
        float2 by = __ldg((const float2*)(b + 320) + tg);
#pragma unroll
        for (int j = 0; j < 4; j++) {
            int P = pairbase + j;
            float y0e0, y0e1, y1e0, y1e1;
            unpack2(yacc[j],     y0e0, y0e1);   // m = tg*2
            unpack2(yacc[4 + j], y1e0, y1e1);   // m = tg*2+1
            *(float2*)(out + (size_t)(b0 + 2 * P) * 32 + tg * 2) =
                make_float2(y0e0 + by.x, y1e0 + by.y);
            *(float2*)(out + (size_t)(b0 + 2 * P + 1) * 32 + tg * 2) =
                make_float2(y0e1 + by.x, y1e1 + by.y);
        }
    }
}

// ---------------- launch ----------------

extern "C" void kernel_launch(void* const* d_in, const int* in_sizes, int n_in,
                              void* d_out, int out_size) {
    const float* u    = (const float*)d_in[0];
    const float* x0   = (const float*)d_in[1];
    const float* B2   = (const float*)d_in[2];
    const float* C2   = (const float*)d_in[3];
    const float* D12  = (const float*)d_in[4];
    const float* D21  = (const float*)d_in[5];
    const float* b    = (const float*)d_in[6];
    const float* X    = (const float*)d_in[7];
    // d_in[8] = Y1 (unused by reference)
    const float* St   = (const float*)d_in[9];
    const float* Q    = (const float*)d_in[10];
    const float* Rinv = (const float*)d_in[11];
    float* out = (float*)d_out;

    k_build_lT<<<NZ, 64>>>(B2, C2, D12, D21, St);
    k_build_M<<<NZ, 64>>>(Rinv, Q);
    k_build_H<<<(256 * 320) / 128, 128>>>(X);
    k_finalize<<<320, 128>>>(D12, D21, C2, b);

    const size_t shbytes = (size_t)SM_TOTAL * sizeof(ULL);   // 113408 B
    cudaFuncSetAttribute(k_main, cudaFuncAttributeMaxDynamicSharedMemorySize, (int)shbytes);
    k_main<<<BATCH / EPB, TB, shbytes>>>(u, x0, b, out);
}

// round 13
// speedup vs baseline: 1.0018x; 1.0018x over previous
#include <cuda_runtime.h>
#include <math.h>

#define NX 64
#define NUN 256
#define NY 32
#define NZ 384        // 2*NX + NUN
#define BATCH 32768
#define NSTATE 384    // 128 (z = x||u) + 256 (w)
#define EPB 64        // batch elements per block (32 pairs)
#define TB 128        // 4 warps; warp owns 8 pairs
#define SSTRIDE 33    // state row stride in ULL (conflict-free for tg16 split)

typedef unsigned long long ULL;

// ---------------- f32x2 / misc helpers ----------------------------------
__device__ __forceinline__ ULL ffma2(ULL a, ULL b, ULL c) {
    ULL d; asm("fma.rn.f32x2 %0, %1, %2, %3;" : "=l"(d) : "l"(a), "l"(b), "l"(c)); return d;
}
__device__ __forceinline__ ULL fadd2(ULL a, ULL b) {
    ULL d; asm("add.rn.f32x2 %0, %1, %2;" : "=l"(d) : "l"(a), "l"(b)); return d;
}
__device__ __forceinline__ ULL pack2(float lo, float hi) {
    ULL d; asm("mov.b64 %0, {%1,%2};" : "=l"(d) : "f"(lo), "f"(hi)); return d;
}
__device__ __forceinline__ void unpack2(ULL v, float& lo, float& hi) {
    asm("mov.b64 {%0,%1}, %2;" : "=f"(lo), "=f"(hi) : "l"(v));
}
__device__ __forceinline__ ULL shfl_xor64(ULL v, int m) {
    return __shfl_xor_sync(0xFFFFFFFFu, v, m, 32);
}
__device__ __forceinline__ float tanh_fast(float x) {
    float y; asm("tanh.approx.f32 %0, %1;" : "=f"(y) : "f"(x)); return y;
}

// ---------------- device scratch (no cudaMalloc allowed) ----------------
__device__ __align__(16) float g_lT1[NZ * 64];
__device__ __align__(16) float g_lT2[NZ * 32];
__device__ __align__(16) float g_M1[NZ * 64];
__device__ __align__(16) float g_M2[NZ * 32];
__device__ __align__(16) float g_H[256 * 320];      // H[64+r][c], c in [0,320)
// per-chunk block (3152 floats):
//   [0,3072)      coefT[t][k]: coefficient for unit k at input row t
//   [3072,3080)   bias (b_w/lam) for k=0..7
//   [3080,3108)   compact diag: dg(k,j) at 3080 + k(k-1)/2 + j, j<k
//   [3108,3152)   pad
__device__ __align__(16) float g_CHUNK[32 * 3152];
// y-weights: rows 0..63 = C2T (x part), 64..319 = D21T (w part)
__device__ __align__(16) float g_YWP[320 * 32];

// ---------------- setup kernels (batch-independent weights) --------------

__global__ void k_build_lT(const float* __restrict__ B2, const float* __restrict__ C2,
                           const float* __restrict__ D12, const float* __restrict__ D21,
                           const float* __restrict__ St) {
    int r = blockIdx.x;      // 0..383
    int k = threadIdx.x;     // 0..63
    float v1;
    if (r < 64) {
        float s = 0.f;
        for (int m = 0; m < 32; m++) s += St[k * 32 + m] * C2[m * 64 + r];
        v1 = s;
    } else if (r < 320) {
        int rr = r - 64;
        float s = 0.f;
        for (int m = 0; m < 32; m++) s += St[k * 32 + m] * D21[m * 256 + rr];
        v1 = s - D12[rr * 64 + k];
    } else {
        v1 = B2[(r - 320) * 64 + k];
    }
    g_lT1[r * 64 + k] = v1;
    if (k < 32) {
        float v2;
        if (r < 64)        v2 = C2[k * 64 + r];
        else if (r < 320)  v2 = D21[k * 256 + (r - 64)];
        else               v2 = 0.f;
        g_lT2[r * 32 + k] = v2;
    }
}

__global__ void k_build_M(const float* __restrict__ Rinv, const float* __restrict__ Q) {
    int r = blockIdx.x, k = threadIdx.x;
    float s = 0.f;
    for (int t = 0; t < 64; t++) s += g_lT1[r * 64 + t] * Rinv[t * 64 + k];
    g_M1[r * 64 + k] = s;
    if (k < 32) {
        float s2 = 0.f;
        for (int t = 0; t < 32; t++) s2 += g_lT2[r * 32 + t] * Q[t * 32 + k];
        g_M2[r * 32 + k] = s2;
    }
}

__global__ void k_build_H(const float* __restrict__ X) {
    int idx = blockIdx.x * blockDim.x + threadIdx.x;
    if (idx >= 256 * 320) return;
    int r = idx / 320, c = idx % 320;
    int a = 64 + r;
    float h = 0.f;
    for (int t = 0; t < NZ; t++) h += X[t * NZ + a] * X[t * NZ + c];
    if (c == a) h += 0.001f;
    float h1 = 0.f;
    for (int k = 0; k < 64; k++) h1 += g_M1[a * 64 + k] * g_lT1[c * 64 + k];
    float h2 = 0.f;
    for (int k = 0; k < 32; k++) h2 += g_M2[a * 32 + k] * g_lT2[c * 32 + k];
    g_H[idx] = h + h1 - h2;
}

// grid 320: i<64 -> C2T rows of g_YWP; else unit uu -> g_CHUNK slices + D21T
__global__ void k_finalize(const float* __restrict__ D12, const float* __restrict__ D21,
                           const float* __restrict__ C2, const float* __restrict__ b) {
    int i = blockIdx.x;
    int tx = threadIdx.x;
    if (i < 64) {
        if (tx < 32) g_YWP[i * 32 + tx] = C2[tx * 64 + i];
        return;
    }
    int uu = i - 64;  // 0..255
    __shared__ float s_inv;
    if (tx == 0) {
        float lam = 0.5f * g_H[uu * 320 + 64 + uu];
        s_inv = 1.f / lam;
    }
    __syncthreads();
    float inv = s_inv;
    int c = uu >> 3, k = uu & 7;
    float* chunk = g_CHUNK + (size_t)c * 3152;
    for (int t = tx; t < NSTATE; t += blockDim.x) {
        float val;
        if (t < 64) {
            val = -g_H[uu * 320 + t] * inv;                 // C_1 / lam
        } else if (t < 128) {
            val = D12[uu * 64 + (t - 64)] * inv;            // D_12 / lam
        } else {
            int j = t - 128;
            val = (uu >= 1 && j <= uu - 2) ? (-g_H[(uu - 1) * 320 + 64 + j]) * inv : 0.f;
        }
        chunk[t * 8 + k] = val;                             // [t][unit] layout
    }
    // compact within-chunk diag: entries (k, j) with j < k
    if (tx < k) {
        int j = c * 8 + tx;   // global column
        float val = (uu >= 1 && j <= uu - 2) ? (-g_H[(uu - 1) * 320 + 64 + j]) * inv : 0.f;
        chunk[3080 + (k * (k - 1)) / 2 + tx] = val;
    }
    if (tx == 0) chunk[3072 + k] = b[64 + uu] * inv;
    if (tx < 32) g_YWP[(64 + uu) * 32 + tx] = D21[tx * 256 + uu];
}

// ---------------- main kernel ---------------------------------------------
// 64 elems = 32 f32x2 pairs per block, 128 threads = 4 warps, warp owns 8
// pairs. lane = pg*16 + tg: pg in {0,1} -> 4 pairs, tg in 0..15 splits the
// t-dimension 16 ways. Lane register tile: 8 units x 4 pairs (32 f32x2 accs).
// Per t-iter: 4 LDS.64 state (native pairs) + 2 LDS.128 coef (8 floats)
// -> 32 FFMA2. Reduce over tg with 4 shfl_xor rounds; diag+tanh on tg==0
// lanes; w-stores warp-local. 2 block barriers/chunk (coef staging only).
//
// Shared layout (ULL units):
#define SM_STATE 0                          // ULL[384][33]   = 12672
#define SM_CA    12672                      // float[376*4]   = 752 ULL
#define SM_CB    (SM_CA + 752)              // float[376*4]   = 752 ULL
#define SM_TOTAL (SM_CB + 752)              // 14176 ULL = 113408 B -> 2 blocks/SM

__global__ void __launch_bounds__(TB, 2)
k_main(const float* __restrict__ u, const float* __restrict__ x0,
       const float* __restrict__ b, float* __restrict__ out) {
    extern __shared__ ULL sh[];
    ULL*   s_state = sh;
    float* s_cA    = (float*)(sh + SM_CA);
    float* s_cB    = (float*)(sh + SM_CB);

    const int tid  = threadIdx.x;
    const int lane = tid & 31;
    const int warp = tid >> 5;
    const int tg   = lane & 15;
    const int pg   = lane >> 4;
    const int pairbase = warp * 8 + pg * 4;   // first of this lane's 4 pairs
    const int b0   = blockIdx.x * EPB;

    // ---- load z = [x(64) | u(64)] coalesced, transposed to pair layout ----
    {
        float* st = (float*)s_state;
#pragma unroll 4
        for (int i = 0; i < 32; i++) {
            int idx = i * TB + tid;          // 0..4095
            int e = idx >> 6, k = idx & 63;
            st[k * 66 + e]        = x0[(size_t)b0 * 64 + idx];
            st[(64 + k) * 66 + e] = u[(size_t)b0 * 64 + idx];
        }
    }

    // ================= main chunk loop =================
    for (int c = 0; c < 32; c++) {
        const float* gchunk = g_CHUNK + (size_t)c * 3152;
        const int T = 128 + 8 * c;

        __syncthreads();   // bar1: prior p-loop done reading coef buffers (and z visible)

        // ---- stage coef chunk c: [t][0..3] -> s_cA, [t][4..7] -> s_cB ----
        for (int idx = tid; idx < T * 2; idx += TB) {
            int t = idx >> 1, h = idx & 1;
            float4 v = __ldg((const float4*)gchunk + t * 2 + h);
            ((float4*)(h ? s_cB : s_cA))[t] = v;
        }

        // ---- prefetch bias(8) + compact diag(28) into regs ----
        float dgb[36];
        {
            const float4* ds = (const float4*)(gchunk + 3072);
#pragma unroll
            for (int i = 0; i < 9; i++) {
                float4 v = __ldg(ds + i);
                dgb[4 * i + 0] = v.x; dgb[4 * i + 1] = v.y;
                dgb[4 * i + 2] = v.z; dgb[4 * i + 3] = v.w;
            }
        }
        __syncthreads();   // bar2: staged coef visible

        // ---- t-loop: lane handles t = tg, tg+16, ... ----
        ULL acc[32];       // acc[k*4+j]: unit k, pair j
#pragma unroll
        for (int i = 0; i < 32; i++) acc[i] = 0ull;

        const ULL* sp   = s_state + (size_t)tg * SSTRIDE + pairbase;
        const float4* ca = (const float4*)s_cA + tg;
        const float4* cb = (const float4*)s_cB + tg;
        for (int t = tg; t < T; t += 16) {
            ULL sv0 = sp[0], sv1 = sp[1], sv2 = sp[2], sv3 = sp[3];
            float4 a4 = *ca;
            float4 b4 = *cb;
            sp += SSTRIDE * 16; ca += 16; cb += 16;
            ULL c0 = pack2(a4.x, a4.x), c1 = pack2(a4.y, a4.y);
            ULL c2 = pack2(a4.z, a4.z), c3 = pack2(a4.w, a4.w);
            ULL c4 = pack2(b4.x, b4.x), c5 = pack2(b4.y, b4.y);
            ULL c6 = pack2(b4.z, b4.z), c7 = pack2(b4.w, b4.w);
#define ACC_K(K, CK) \
            acc[(K)*4+0] = ffma2(sv0, CK, acc[(K)*4+0]); \
            acc[(K)*4+1] = ffma2(sv1, CK, acc[(K)*4+1]); \
            acc[(K)*4+2] = ffma2(sv2, CK, acc[(K)*4+2]); \
            acc[(K)*4+3] = ffma2(sv3, CK, acc[(K)*4+3]);
            ACC_K(0, c0) ACC_K(1, c1) ACC_K(2, c2) ACC_K(3, c3)
            ACC_K(4, c4) ACC_K(5, c5) ACC_K(6, c6) ACC_K(7, c7)
#undef ACC_K
        }

        // ---- reduce over tg: 4 shfl_xor rounds ----
#pragma unroll
        for (int i = 0; i < 32; i++) {
            acc[i] = fadd2(acc[i], shfl_xor64(acc[i], 1));
            acc[i] = fadd2(acc[i], shfl_xor64(acc[i], 2));
            acc[i] = fadd2(acc[i], shfl_xor64(acc[i], 4));
            acc[i] = fadd2(acc[i], shfl_xor64(acc[i], 8));
        }

        // ---- serial 8x8 diag + tanh + store w (tg==0 lanes only) ----
        if (tg == 0) {
            ULL wl[32];
#pragma unroll
            for (int k = 0; k < 8; k++) {
                ULL bk = pack2(dgb[k], dgb[k]);
                ULL s0 = fadd2(acc[k * 4 + 0], bk);
                ULL s1 = fadd2(acc[k * 4 + 1], bk);
                ULL s2 = fadd2(acc[k * 4 + 2], bk);
                ULL s3 = fadd2(acc[k * 4 + 3], bk);
#pragma unroll
                for (int ju = 0; ju < 7; ju++) {
                    if (ju < k) {
                        float d = dgb[8 + (k * (k - 1)) / 2 + ju];
                        ULL dd = pack2(d, d);
                        s0 = ffma2(wl[ju * 4 + 0], dd, s0);
                        s1 = ffma2(wl[ju * 4 + 1], dd, s1);
                        s2 = ffma2(wl[ju * 4 + 2], dd, s2);
                        s3 = ffma2(wl[ju * 4 + 3], dd, s3);
                    }
                }
                float l0, h0, l1, h1, l2, h2, l3, h3;
                unpack2(s0, l0, h0); unpack2(s1, l1, h1);
                unpack2(s2, l2, h2); unpack2(s3, l3, h3);
                wl[k * 4 + 0] = pack2(tanh_fast(l0), tanh_fast(h0));
                wl[k * 4 + 1] = pack2(tanh_fast(l1), tanh_fast(h1));
                wl[k * 4 + 2] = pack2(tanh_fast(l2), tanh_fast(h2));
                wl[k * 4 + 3] = pack2(tanh_fast(l3), tanh_fast(h3));
                ULL* wrow = s_state + (size_t)(128 + c * 8 + k) * SSTRIDE + pairbase;
                wrow[0] = wl[k * 4 + 0]; wrow[1] = wl[k * 4 + 1];
                wrow[2] = wl[k * 4 + 2]; wrow[3] = wl[k * 4 + 3];
            }
        }
        __syncwarp();   // w(c) visible within warp (state cols are warp-private)
    }

    // ================= y-tail: y = x@C2T + w@D21T =================
    // lane covers m = {tg*2, tg*2+1} for its 4 pairs; rows staged in 4 rounds.
    ULL yacc[8];   // yacc[mm*4 + j]
#pragma unroll
    for (int i = 0; i < 8; i++) yacc[i] = 0ull;
    float* yc = (float*)(sh + SM_CA);   // 3008-float region (needs 2560)

    for (int r = 0; r < 4; r++) {
        __syncthreads();
        {
            const float4* src = (const float4*)g_YWP + r * 640;
#pragma unroll
            for (int i = 0; i < 5; i++) ((float4*)yc)[i * TB + tid] = __ldg(src + i * TB + tid);
        }
        __syncthreads();
#pragma unroll 2
        for (int i = 0; i < 80; i++) {
            int g = r * 80 + i;
            int srow = (g < 64) ? g : g + 64;
            const ULL* sp2 = s_state + (size_t)srow * SSTRIDE + pairbase;
            ULL sv0 = sp2[0], sv1 = sp2[1], sv2 = sp2[2], sv3 = sp2[3];
            float2 cm = *(const float2*)(yc + i * 32 + tg * 2);
            ULL cm0 = pack2(cm.x, cm.x), cm1 = pack2(cm.y, cm.y);
            yacc[0] = ffma2(sv0, cm0, yacc[0]);
            yacc[1] = ffma2(sv1, cm0, yacc[1]);
            yacc[2] = ffma2(sv2, cm0, yacc[2]);
            yacc[3] = ffma2(sv3, cm0, yacc[3]);
            yacc[4] = ffma2(sv0, cm1, yacc[4]);
            yacc[5] = ffma2(sv1, cm1, yacc[5]);
            yacc[6] = ffma2(sv2, cm1, yacc[6]);
            yacc[7] = ffma2(sv3, cm1, yacc[7]);
        }
    }

    // ---- output: lane stores m-pair (tg*2, tg*2+1) for its 8 elems ----
    {
        float2 by = __ldg((const float2*)(b + 320) + tg);
#pragma unroll
        for (int j = 0; j < 4; j++) {
            int P = pairbase + j;
            float y0e0, y0e1, y1e0, y1e1;
            unpack2(yacc[j],     y0e0, y0e1);   // m = tg*2
            unpack2(yacc[4 + j], y1e0, y1e1);   // m = tg*2+1
            *(float2*)(out + (size_t)(b0 + 2 * P) * 32 + tg * 2) =
                make_float2(y0e0 + by.x, y1e0 + by.y);
            *(float2*)(out + (size_t)(b0 + 2 * P + 1) * 32 + tg * 2) =
                make_float2(y0e1 + by.x, y1e1 + by.y);
        }
    }
}

// ---------------- launch ----------------

extern "C" void kernel_launch(void* const* d_in, const int* in_sizes, int n_in,
                              void* d_out, int out_size) {
    const float* u    = (const float*)d_in[0];
    const float* x0   = (const float*)d_in[1];
    const float* B2   = (const float*)d_in[2];
    const float* C2   = (const float*)d_in[3];
    const float* D12  = (const float*)d_in[4];
    const float* D21  = (const float*)d_in[5];
    const float* b    = (const float*)d_in[6];
    const float* X    = (const float*)d_in[7];
    // d_in[8] = Y1 (unused by reference)
    const float* St   = (const float*)d_in[9];
    const float* Q    = (const float*)d_in[10];
    const float* Rinv = (const float*)d_in[11];
    float* out = (float*)d_out;

    k_build_lT<<<NZ, 64>>>(B2, C2, D12, D21, St);
    k_build_M<<<NZ, 64>>>(Rinv, Q);
    k_build_H<<<(256 * 320) / 128, 128>>>(X);
    k_finalize<<<320, 128>>>(D12, D21, C2, b);

    const size_t shbytes = (size_t)SM_TOTAL * sizeof(ULL);   // 113408 B
    cudaFuncSetAttribute(k_main, cudaFuncAttributeMaxDynamicSharedMemorySize, (int)shbytes);
    k_main<<<BATCH / EPB, TB, shbytes>>>(u, x0, b, out);
}

// round 14
// speedup vs baseline: 1.0041x; 1.0024x over previous
#include <cuda_runtime.h>
#include <math.h>

#define NX 64
#define NUN 256
#define NY 32
#define NZ 384        // 2*NX + NUN
#define BATCH 32768
#define NSTATE 384    // 128 (z = x||u) + 256 (w)
#define EPB 64        // batch elements per block (32 pairs)
#define TB 128        // 4 warps; warp owns 8 pairs
#define SSTRIDE 33    // state row stride in ULL (conflict-free for tg16 split)

typedef unsigned long long ULL;

// ---------------- f32x2 / misc helpers ----------------------------------
__device__ __forceinline__ ULL ffma2(ULL a, ULL b, ULL c) {
    ULL d; asm("fma.rn.f32x2 %0, %1, %2, %3;" : "=l"(d) : "l"(a), "l"(b), "l"(c)); return d;
}
__device__ __forceinline__ ULL fadd2(ULL a, ULL b) {
    ULL d; asm("add.rn.f32x2 %0, %1, %2;" : "=l"(d) : "l"(a), "l"(b)); return d;
}
__device__ __forceinline__ ULL pack2(float lo, float hi) {
    ULL d; asm("mov.b64 %0, {%1,%2};" : "=l"(d) : "f"(lo), "f"(hi)); return d;
}
__device__ __forceinline__ void unpack2(ULL v, float& lo, float& hi) {
    asm("mov.b64 {%0,%1}, %2;" : "=f"(lo), "=f"(hi) : "l"(v));
}
__device__ __forceinline__ ULL shfl_xor64(ULL v, int m) {
    return __shfl_xor_sync(0xFFFFFFFFu, v, m, 32);
}
__device__ __forceinline__ float tanh_fast(float x) {
    float y; asm("tanh.approx.f32 %0, %1;" : "=f"(y) : "f"(x)); return y;
}

// ---------------- device scratch (no cudaMalloc allowed) ----------------
__device__ __align__(16) float g_lT1[NZ * 64];
__device__ __align__(16) float g_lT2[NZ * 32];
__device__ __align__(16) float g_M1[NZ * 64];
__device__ __align__(16) float g_M2[NZ * 32];
__device__ __align__(16) float g_H[256 * 320];      // H[64+r][c], c in [0,320)
// per-chunk block (3152 floats):
//   [0,3072)      coefT[t][k]: coefficient for unit k at input row t
//   [3072,3080)   bias (b_w/lam) for k=0..7
//   [3080,3108)   compact diag: dg(k,j) at 3080 + k(k-1)/2 + j, j<k
//   [3108,3152)   pad
__device__ __align__(16) float g_CHUNK[32 * 3152];
// y-weights: rows 0..63 = C2T (x part), 64..319 = D21T (w part)
__device__ __align__(16) float g_YWP[320 * 32];

// ---------------- setup kernels (batch-independent weights) --------------

__global__ void k_build_lT(const float* __restrict__ B2, const float* __restrict__ C2,
                           const float* __restrict__ D12, const float* __restrict__ D21,
                           const float* __restrict__ St) {
    int r = blockIdx.x;      // 0..383
    int k = threadIdx.x;     // 0..63
    float v1;
    if (r < 64) {
        float s = 0.f;
        for (int m = 0; m < 32; m++) s += St[k * 32 + m] * C2[m * 64 + r];
        v1 = s;
    } else if (r < 320) {
        int rr = r - 64;
        float s = 0.f;
        for (int m = 0; m < 32; m++) s += St[k * 32 + m] * D21[m * 256 + rr];
        v1 = s - D12[rr * 64 + k];
    } else {
        v1 = B2[(r - 320) * 64 + k];
    }
    g_lT1[r * 64 + k] = v1;
    if (k < 32) {
        float v2;
        if (r < 64)        v2 = C2[k * 64 + r];
        else if (r < 320)  v2 = D21[k * 256 + (r - 64)];
        else               v2 = 0.f;
        g_lT2[r * 32 + k] = v2;
    }
}

__global__ void k_build_M(const float* __restrict__ Rinv, const float* __restrict__ Q) {
    int r = blockIdx.x, k = threadIdx.x;
    float s = 0.f;
    for (int t = 0; t < 64; t++) s += g_lT1[r * 64 + t] * Rinv[t * 64 + k];
    g_M1[r * 64 + k] = s;
    if (k < 32) {
        float s2 = 0.f;
        for (int t = 0; t < 32; t++) s2 += g_lT2[r * 32 + t] * Q[t * 32 + k];
        g_M2[r * 32 + k] = s2;
    }
}

__global__ void k_build_H(const float* __restrict__ X) {
    int idx = blockIdx.x * blockDim.x + threadIdx.x;
    if (idx >= 256 * 320) return;
    int r = idx / 320, c = idx % 320;
    int a = 64 + r;
    float h = 0.f;
    for (int t = 0; t < NZ; t++) h += X[t * NZ + a] * X[t * NZ + c];
    if (c == a) h += 0.001f;
    float h1 = 0.f;
    for (int k = 0; k < 64; k++) h1 += g_M1[a * 64 + k] * g_lT1[c * 64 + k];
    float h2 = 0.f;
    for (int k = 0; k < 32; k++) h2 += g_M2[a * 32 + k] * g_lT2[c * 32 + k];
    g_H[idx] = h + h1 - h2;
}

// grid 320: i<64 -> C2T rows of g_YWP; else unit uu -> g_CHUNK slices + D21T
__global__ void k_finalize(const float* __restrict__ D12, const float* __restrict__ D21,
                           const float* __restrict__ C2, const float* __restrict__ b) {
    int i = blockIdx.x;
    int tx = threadIdx.x;
    if (i < 64) {
        if (tx < 32) g_YWP[i * 32 + tx] = C2[tx * 64 + i];
        return;
    }
    int uu = i - 64;  // 0..255
    __shared__ float s_inv;
    if (tx == 0) {
        float lam = 0.5f * g_H[uu * 320 + 64 + uu];
        s_inv = 1.f / lam;
    }
    __syncthreads();
    float inv = s_inv;
    int c = uu >> 3, k = uu & 7;
    float* chunk = g_CHUNK + (size_t)c * 3152;
    for (int t = tx; t < NSTATE; t += blockDim.x) {
        float val;
        if (t < 64) {
            val = -g_H[uu * 320 + t] * inv;                 // C_1 / lam
        } else if (t < 128) {
            val = D12[uu * 64 + (t - 64)] * inv;            // D_12 / lam
        } else {
            int j = t - 128;
            val = (uu >= 1 && j <= uu - 2) ? (-g_H[(uu - 1) * 320 + 64 + j]) * inv : 0.f;
        }
        chunk[t * 8 + k] = val;                             // [t][unit] layout
    }
    // compact within-chunk diag: entries (k, j) with j < k
    if (tx < k) {
        int j = c * 8 + tx;   // global column
        float val = (uu >= 1 && j <= uu - 2) ? (-g_H[(uu - 1) * 320 + 64 + j]) * inv : 0.f;
        chunk[3080 + (k * (k - 1)) / 2 + tx] = val;
    }
    if (tx == 0) chunk[3072 + k] = b[64 + uu] * inv;
    if (tx < 32) g_YWP[(64 + uu) * 32 + tx] = D21[tx * 256 + uu];
}

// ---------------- main kernel ---------------------------------------------
// 64 elems = 32 f32x2 pairs per block, 128 threads = 4 warps, warp owns 8
// pairs. lane = pg*16 + tg: pg in {0,1} -> 4 pairs, tg in 0..15 splits the
// t-dimension 16 ways. Lane register tile: 8 units x 4 pairs (32 f32x2 accs).
// Per t-iter: 4 LDS.64 state (native pairs) + 2 LDS.128 coef (8 floats)
// -> 32 FFMA2. Reduce over tg with 4 shfl_xor rounds; diag+tanh on tg==0
// lanes; w-stores warp-local. 2 block barriers/chunk (coef staging only).
//
// Shared layout (ULL units):
#define SM_STATE 0                          // ULL[384][33]   = 12672
#define SM_CA    12672                      // float[376*4]   = 752 ULL
#define SM_CB    (SM_CA + 752)              // float[376*4]   = 752 ULL
#define SM_TOTAL (SM_CB + 752)              // 14176 ULL = 113408 B -> 2 blocks/SM

__global__ void __launch_bounds__(TB, 2)
k_main(const float* __restrict__ u, const float* __restrict__ x0,
       const float* __restrict__ b, float* __restrict__ out) {
    extern __shared__ ULL sh[];
    ULL*   s_state = sh;
    float* s_cA    = (float*)(sh + SM_CA);
    float* s_cB    = (float*)(sh + SM_CB);

    const int tid  = threadIdx.x;
    const int lane = tid & 31;
    const int warp = tid >> 5;
    const int tg   = lane & 15;
    const int pg   = lane >> 4;
    const int pairbase = warp * 8 + pg * 4;   // first of this lane's 4 pairs
    const int b0   = blockIdx.x * EPB;

    // ---- load z = [x(64) | u(64)] coalesced, transposed to pair layout ----
    {
        float* st = (float*)s_state;
#pragma unroll 4
        for (int i = 0; i < 32; i++) {
            int idx = i * TB + tid;          // 0..4095
            int e = idx >> 6, k = idx & 63;
            st[k * 66 + e]        = x0[(size_t)b0 * 64 + idx];
            st[(64 + k) * 66 + e] = u[(size_t)b0 * 64 + idx];
        }
    }

    // ================= main chunk loop =================
    for (int c = 0; c < 32; c++) {
        const float* gchunk = g_CHUNK + (size_t)c * 3152;
        const int T = 128 + 8 * c;

        __syncthreads();   // bar1: prior p-loop done reading coef buffers (and z visible)

        // ---- stage coef chunk c: [t][0..3] -> s_cA, [t][4..7] -> s_cB ----
        for (int idx = tid; idx < T * 2; idx += TB) {
            int t = idx >> 1, h = idx & 1;
            float4 v = __ldg((const float4*)gchunk + t * 2 + h);
            ((float4*)(h ? s_cB : s_cA))[t] = v;
        }

        // ---- prefetch bias(8) + compact diag(28) into regs ----
        float dgb[36];
        {
            const float4* ds = (const float4*)(gchunk + 3072);
#pragma unroll
            for (int i = 0; i < 9; i++) {
                float4 v = __ldg(ds + i);
                dgb[4 * i + 0] = v.x; dgb[4 * i + 1] = v.y;
                dgb[4 * i + 2] = v.z; dgb[4 * i + 3] = v.w;
            }
        }
        __syncthreads();   // bar2: staged coef visible

        // ---- t-loop: lane handles t = tg, tg+16, ... ----
        ULL acc[32];       // acc[k*4+j]: unit k, pair j
#pragma unroll
        for (int i = 0; i < 32; i++) acc[i] = 0ull;

        const ULL* sp   = s_state + (size_t)tg * SSTRIDE + pairbase;
        const float4* ca = (const float4*)s_cA + tg;
        const float4* cb = (const float4*)s_cB + tg;
        for (int t = tg; t < T; t += 16) {
            ULL sv0 = sp[0], sv1 = sp[1], sv2 = sp[2], sv3 = sp[3];
            float4 a4 = *ca;
            float4 b4 = *cb;
            sp += SSTRIDE * 16; ca += 16; cb += 16;
            ULL c0 = pack2(a4.x, a4.x), c1 = pack2(a4.y, a4.y);
            ULL c2 = pack2(a4.z, a4.z), c3 = pack2(a4.w, a4.w);
            ULL c4 = pack2(b4.x, b4.x), c5 = pack2(b4.y, b4.y);
            ULL c6 = pack2(b4.z, b4.z), c7 = pack2(b4.w, b4.w);
#define ACC_K(K, CK) \
            acc[(K)*4+0] = ffma2(sv0, CK, acc[(K)*4+0]); \
            acc[(K)*4+1] = ffma2(sv1, CK, acc[(K)*4+1]); \
            acc[(K)*4+2] = ffma2(sv2, CK, acc[(K)*4+2]); \
            acc[(K)*4+3] = ffma2(sv3, CK, acc[(K)*4+3]);
            ACC_K(0, c0) ACC_K(1, c1) ACC_K(2, c2) ACC_K(3, c3)
            ACC_K(4, c4) ACC_K(5, c5) ACC_K(6, c6) ACC_K(7, c7)
#undef ACC_K
        }

        // ---- reduce over tg: 4 shfl_xor rounds ----
#pragma unroll
        for (int i = 0; i < 32; i++) {
            acc[i] = fadd2(acc[i], shfl_xor64(acc[i], 1));
            acc[i] = fadd2(acc[i], shfl_xor64(acc[i], 2));
            acc[i] = fadd2(acc[i], shfl_xor64(acc[i], 4));
            acc[i] = fadd2(acc[i], shfl_xor64(acc[i], 8));
        }

        // ---- serial 8x8 diag + tanh + store w (tg==0 lanes only) ----
        if (tg == 0) {
            ULL wl[32];
#pragma unroll
            for (int k = 0; k < 8; k++) {
                ULL bk = pack2(dgb[k], dgb[k]);
                ULL s0 = fadd2(acc[k * 4 + 0], bk);
                ULL s1 = fadd2(acc[k * 4 + 1], bk);
                ULL s2 = fadd2(acc[k * 4 + 2], bk);
                ULL s3 = fadd2(acc[k * 4 + 3], bk);
#pragma unroll
                for (int ju = 0; ju < 7; ju++) {
                    if (ju < k) {
                        float d = dgb[8 + (k * (k - 1)) / 2 + ju];
                        ULL dd = pack2(d, d);
                        s0 = ffma2(wl[ju * 4 + 0], dd, s0);
                        s1 = ffma2(wl[ju * 4 + 1], dd, s1);
                        s2 = ffma2(wl[ju * 4 + 2], dd, s2);
                        s3 = ffma2(wl[ju * 4 + 3], dd, s3);
                    }
                }
                float l0, h0, l1, h1, l2, h2, l3, h3;
                unpack2(s0, l0, h0); unpack2(s1, l1, h1);
                unpack2(s2, l2, h2); unpack2(s3, l3, h3);
                wl[k * 4 + 0] = pack2(tanh_fast(l0), tanh_fast(h0));
                wl[k * 4 + 1] = pack2(tanh_fast(l1), tanh_fast(h1));
                wl[k * 4 + 2] = pack2(tanh_fast(l2), tanh_fast(h2));
                wl[k * 4 + 3] = pack2(tanh_fast(l3), tanh_fast(h3));
                ULL* wrow = s_state + (size_t)(128 + c * 8 + k) * SSTRIDE + pairbase;
                wrow[0] = wl[k * 4 + 0]; wrow[1] = wl[k * 4 + 1];
                wrow[2] = wl[k * 4 + 2]; wrow[3] = wl[k * 4 + 3];
            }
        }
        __syncwarp();   // w(c) visible within warp (state cols are warp-private)
    }

    // ================= y-tail: y = x@C2T + w@D21T =================
    // lane covers m = {tg*2, tg*2+1} for its 4 pairs; rows staged in 4 rounds.
    ULL yacc[8];   // yacc[mm*4 + j]
#pragma unroll
    for (int i = 0; i < 8; i++) yacc[i] = 0ull;
    float* yc = (float*)(sh + SM_CA);   // 3008-float region (needs 2560)

    for (int r = 0; r < 4; r++) {
        __syncthreads();
        {
            const float4* src = (const float4*)g_YWP + r * 640;
#pragma unroll
            for (int i = 0; i < 5; i++) ((float4*)yc)[i * TB + tid] = __ldg(src + i * TB + tid);
        }
        __syncthreads();
#pragma unroll 2
        for (int i = 0; i < 80; i++) {
            int g = r * 80 + i;
            int srow = (g < 64) ? g : g + 64;
            const ULL* sp2 = s_state + (size_t)srow * SSTRIDE + pairbase;
            ULL sv0 = sp2[0], sv1 = sp2[1], sv2 = sp2[2], sv3 = sp2[3];
            float2 cm = *(const float2*)(yc + i * 32 + tg * 2);
            ULL cm0 = pack2(cm.x, cm.x), cm1 = pack2(cm.y, cm.y);
            yacc[0] = ffma2(sv0, cm0, yacc[0]);
            yacc[1] = ffma2(sv1, cm0, yacc[1]);
            yacc[2] = ffma2(sv2, cm0, yacc[2]);
            yacc[3] = ffma2(sv3, cm0, yacc[3]);
            yacc[4] = ffma2(sv0, cm1, yacc[4]);
            yacc[5] = ffma2(sv1, cm1, yacc[5]);
            yacc[6] = ffma2(sv2, cm1, yacc[6]);
            yacc[7] = ffma2(sv3, cm1, yacc[7]);
        }
    }

    // ---- output: lane stores m-pair (tg*2, tg*2+1) for its 8 elems ----
    {
        float2 by = __ldg((const float2*)(b + 320) + tg);
#pragma unroll
        for (int j = 0; j < 4; j++) {
            int P = pairbase + j;
            float y0e0, y0e1, y1e0, y1e1;
            unpack2(yacc[j],     y0e0, y0e1);   // m = tg*2
            unpack2(yacc[4 + j], y1e0, y1e1);   // m = tg*2+1
            *(float2*)(out + (size_t)(b0 + 2 * P) * 32 + tg * 2) =
                make_float2(y0e0 + by.x, y1e0 + by.y);
            *(float2*)(out + (size_t)(b0 + 2 * P + 1) * 32 + tg * 2) =
                make_float2(y0e1 + by.x, y1e1 + by.y);
        }
    }
}

// ---------------- launch ----------------

extern "C" void kernel_launch(void* const* d_in, const int* in_sizes, int n_in,
                              void* d_out, int out_size) {
    const float* u    = (const float*)d_in[0];
    const float* x0   = (const float*)d_in[1];
    const float* B2   = (const float*)d_in[2];
    const float* C2   = (const float*)d_in[3];
    const float* D12  = (const float*)d_in[4];
    const float* D21  = (const float*)d_in[5];
    const float* b    = (const float*)d_in[6];
    const float* X    = (const float*)d_in[7];
    // d_in[8] = Y1 (unused by reference)
    const float* St   = (const float*)d_in[9];
    const float* Q    = (const float*)d_in[10];
    const float* Rinv = (const float*)d_in[11];
    float* out = (float*)d_out;

    k_build_lT<<<NZ, 64>>>(B2, C2, D12, D21, St);
    k_build_M<<<NZ, 64>>>(Rinv, Q);
    k_build_H<<<(256 * 320) / 128, 128>>>(X);
    k_finalize<<<320, 128>>>(D12, D21, C2, b);

    const size_t shbytes = (size_t)SM_TOTAL * sizeof(ULL);   // 113408 B
    cudaFuncSetAttribute(k_main, cudaFuncAttributeMaxDynamicSharedMemorySize, (int)shbytes);
    k_main<<<BATCH / EPB, TB, shbytes>>>(u, x0, b, out);
}